// round 15
// baseline (speedup 1.0000x reference)
#include <cuda_runtime.h>
#include <math.h>

#define LEAK 0.2f

__device__ __forceinline__ float leaky_(float x) { return x >= 0.f ? x : LEAK * x; }
__device__ __forceinline__ float sigm_(float x) {
    float e = __expf(-x);
    return __fdividef(1.f, 1.f + e);
}

// Shared weight-arena offsets (floats)
#define OFF_WM1 0
#define OFF_BM1 48
#define OFF_WM2 56
#define OFF_BM2 184
#define OFF_WT1 200
#define OFF_BT1 288
#define OFF_WT2 296
#define OFF_BT2 424
#define OFF_WS1 440
#define OFF_BS1 2296
#define OFF_WS2 2328
#define OFF_BS2 4376
#define OFF_WP2 4440
#define OFF_BP2 6488
#define OFF_WP3 6520
#define OFF_BP3 7032
#define OFF_WP4 7048
#define OFF_BP4 7176
#define OFF_WP5 7184
#define OFF_BP5 7208
#define OFF_BL  7212              /* 512 floats */
#define OFF_BP1 7724              /* 64 floats */
#define OFF_WP1 7788              /* 128 rows x 68 floats (stride-17 float4, padded) */
#define ARENA_SZ (7788 + 128 * 68)

#define WSTRIDE 33   // float4 row stride for Wk/Wr slices (pad kills bank conflicts)

struct SmemT {
    float4 WkS4[128 * WSTRIDE];     // Wk column slice (rows 124..127 zeroed)
    float4 WrS4[128 * WSTRIDE];     // Wr column slice
    float4 zxs4[3][32];             // zx slice per t (includes b_l)
    float4 zbuf4[32];               // recurrence matvec partial
    float  hb[2][128];              // double-buffered full h
    float  warr[ARENA_SZ];          // small weights + b_l + b_P1 + padded W_P1
    unsigned long long mbar;
    alignas(16) float xs[3][11];
    float  M1s[3][8], T1s[3][8];
    alignas(16) float s_in[3][58];
    float  S1s[3][32];
    alignas(16) float lin[3][128];  // cols 124..127 zeroed; 16B-aligned for LDS.128
    float  d1[64], d2[32], d3[16], d4[8], d5[3], probs[3];
};

__device__ __forceinline__ unsigned smem_u32_(const void* p) {
    unsigned a;
    asm("{ .reg .u64 t; cvta.to.shared.u64 t, %1; cvt.u32.u64 %0, t; }" : "=r"(a) : "l"(p));
    return a;
}
__device__ __forceinline__ void cpa16_(unsigned dst, const void* src) {
    asm volatile("cp.async.cg.shared.global [%0], [%1], 16;" :: "r"(dst), "l"(src) : "memory");
}
#define CP_COMMIT() asm volatile("cp.async.commit_group;" ::: "memory")
#define CP_WAIT(n)  asm volatile("cp.async.wait_group %0;" :: "n"(n) : "memory")

__device__ __forceinline__ void st_cluster_f32_(unsigned laddr, unsigned rank, float v) {
    asm volatile("{ .reg .b32 r; mapa.shared::cluster.u32 r, %0, %1; st.shared::cluster.f32 [r], %2; }"
                 :: "r"(laddr), "r"(rank), "f"(v) : "memory");
}
__device__ __forceinline__ void mbar_arrive_rel_(unsigned mb_local, unsigned rank) {
    asm volatile("{ .reg .b32 r; mapa.shared::cluster.u32 r, %0, %1;\n\t"
                 "mbarrier.arrive.release.cluster.shared::cluster.b64 _, [r]; }"
                 :: "r"(mb_local), "r"(rank) : "memory");
}
__device__ __forceinline__ void mbar_wait_parity_(unsigned mb, unsigned parity) {
    asm volatile(
        "{\n\t.reg .pred P;\n"
        "WL_%=:\n\t"
        "mbarrier.try_wait.parity.acquire.cluster.shared::cta.b64 P, [%0], %1, 0x989680;\n\t"
        "@P bra.uni WD_%=;\n\t"
        "bra.uni WL_%=;\n"
        "WD_%=:\n\t}"
        :: "r"(mb), "r"(parity) : "memory");
}

// 4 CTAs per batch (cluster). Rank r owns h[32r..32r+32) and the matching
// z-columns of each i/f/g/o strip. Only timesteps 0..2 matter (out = out[:,2:3,:]).
__global__ __launch_bounds__(256, 1) __cluster_dims__(4, 1, 1)
void lstm_t2_kernel(
    const float* __restrict__ data,
    const float* __restrict__ W_M1, const float* __restrict__ b_M1,
    const float* __restrict__ W_M2, const float* __restrict__ b_M2,
    const float* __restrict__ W_T1, const float* __restrict__ b_T1,
    const float* __restrict__ W_T2, const float* __restrict__ b_T2,
    const float* __restrict__ W_S1, const float* __restrict__ b_S1,
    const float* __restrict__ W_S2, const float* __restrict__ b_S2,
    const float* __restrict__ Wk,   // (124,512)
    const float* __restrict__ Wr,   // (128,512)
    const float* __restrict__ b_l,  // (512)
    const float* __restrict__ W_P1, const float* __restrict__ b_P1,
    const float* __restrict__ W_P2, const float* __restrict__ b_P2,
    const float* __restrict__ W_P3, const float* __restrict__ b_P3,
    const float* __restrict__ W_P4, const float* __restrict__ b_P4,
    const float* __restrict__ W_P5, const float* __restrict__ b_P5,
    float* __restrict__ out)
{
    extern __shared__ char smraw[];
    SmemT& S = *reinterpret_cast<SmemT*>(smraw);

    const int tid  = threadIdx.x;
    const int w    = tid >> 5, lane = tid & 31;
    const int b    = blockIdx.x >> 2;
    const int rank = blockIdx.x & 3;
    const int T = 4096, F = 11;

    // recurrence lane map: dc = row-chunk (8 lanes), jq = float4-col within warp
    const int dc = lane & 7, jq = lane >> 3;
    const int c4  = w * 4 + jq;                                 // slice float4-col 0..31
    // staging map (coalesced in 8-lane groups): slice col `lane` <-> global col gmap
    const int gmap = ((lane >> 3) * 32) + rank * 8 + (lane & 7);

    const unsigned warr_b = smem_u32_(S.warr);
    const unsigned wk_b   = smem_u32_(S.WkS4);
    const unsigned wr_b   = smem_u32_(S.WrS4);
    const unsigned mb     = smem_u32_(&S.mbar);

    if (tid == 0)
        asm volatile("mbarrier.init.shared.b64 [%0], %1;" :: "r"(mb), "r"(4u) : "memory");

    // ---- Group 1: arena (+ b_l, b_P1) ----
#define ACPY(off, src, nfl) { const float4* s4_ = (const float4*)(src); \
    for (int i = tid; i < (nfl) / 4; i += 256) cpa16_(warr_b + ((off) + i * 4) * 4, s4_ + i); }
    ACPY(OFF_WM1, W_M1, 48)   ACPY(OFF_BM1, b_M1, 8)
    ACPY(OFF_WM2, W_M2, 128)  ACPY(OFF_BM2, b_M2, 16)
    ACPY(OFF_WT1, W_T1, 88)   ACPY(OFF_BT1, b_T1, 8)
    ACPY(OFF_WT2, W_T2, 128)  ACPY(OFF_BT2, b_T2, 16)
    ACPY(OFF_WS1, W_S1, 1856) ACPY(OFF_BS1, b_S1, 32)
    ACPY(OFF_WS2, W_S2, 2048) ACPY(OFF_BS2, b_S2, 64)
    ACPY(OFF_BL,  b_l,  512)
    if (rank == 0) {
        ACPY(OFF_WP2, W_P2, 2048) ACPY(OFF_BP2, b_P2, 32)
        ACPY(OFF_WP3, W_P3, 512)  ACPY(OFF_BP3, b_P3, 16)
        ACPY(OFF_WP4, W_P4, 128)  ACPY(OFF_BP4, b_P4, 8)
        ACPY(OFF_WP5, W_P5, 24)   ACPY(OFF_BP1, b_P1, 64)
    }
#undef ACPY
    CP_COMMIT();

    // ---- Group 2: Wk slice ----
    {
        const float4* Wk4 = (const float4*)Wk;   // row stride 128 float4
        #pragma unroll
        for (int k = 0; k < 16; k++) {
            int d = w + 8 * k;
            if (d < 124) cpa16_(wk_b + (d * WSTRIDE + lane) * 16, Wk4 + (size_t)d * 128 + gmap);
        }
    }
    CP_COMMIT();

    // ---- Group 3: Wr slice + padded W_P1 ----
    {
        const float4* Wr4 = (const float4*)Wr;
        #pragma unroll
        for (int k = 0; k < 16; k++) {
            int d = w + 8 * k;
            cpa16_(wr_b + (d * WSTRIDE + lane) * 16, Wr4 + (size_t)d * 128 + gmap);
        }
        if (rank == 0) {
            const float4* Wp14 = (const float4*)W_P1;  // row stride 16 float4
            for (int i = tid; i < 2048; i += 256) {    // 128 rows x 16 chunks
                int row = i >> 4, c = i & 15;
                cpa16_(warr_b + (OFF_WP1 + row * 68 + c * 4) * 4, Wp14 + row * 16 + c);
            }
        }
    }
    CP_COMMIT();

    // zero Wk pad rows, lin pad cols, inputs, b_P5 (overlapped with cp.async)
    if (tid < 132) {
        float4 z = {0.f, 0.f, 0.f, 0.f};
        S.WkS4[(124 + tid / 33) * WSTRIDE + tid % 33] = z;
    } else if (tid >= 160 && tid < 172) {
        int i = tid - 160;
        S.lin[i >> 2][124 + (i & 3)] = 0.f;
    } else if (tid >= 192 && tid < 195) {
        S.warr[OFF_BP5 + tid - 192] = b_P5[tid - 192];
    }
    if (tid < 33) {
        int t = tid / 11, k = tid % 11;
        S.xs[t][k] = data[((size_t)b * T + t) * F + k];
    }

    CP_WAIT(2);          // arena landed
    __syncthreads();
    asm volatile("barrier.cluster.arrive.aligned;" ::: "memory");  // publish mbar init

    // ---- Prologue: warp t (t<3) runs the whole per-timestep chain, warp-local ----
    if (w < 3) {
        const int t = w;
        if (lane < 8) {
            float a = S.warr[OFF_BM1 + lane];
            #pragma unroll
            for (int d = 0; d < 6; d++) a += S.xs[t][4 + d] * S.warr[OFF_WM1 + d * 8 + lane];
            S.M1s[t][lane] = leaky_(a);
        } else if (lane < 16) {
            int j = lane - 8;
            float a = S.warr[OFF_BT1 + j];
            #pragma unroll
            for (int d = 0; d < 11; d++) a += S.xs[t][d] * S.warr[OFF_WT1 + d * 8 + j];
            S.T1s[t][j] = fabsf(leaky_(a));
        } else if (lane < 27) {
            int k = lane - 16;
            S.lin[t][113 + k] = S.xs[t][k];
            if (k < 6) S.s_in[t][52 + k] = S.xs[t][4 + k];
        } else if (lane == 27) {
            S.s_in[t][48] = log1pf(S.xs[t][1]);
        } else if (lane < 31) {
            int k = lane - 28;
            S.s_in[t][49 + k] = S.xs[t][1 + k];
        }
        __syncwarp();
        if (lane < 16) {
            float a = S.warr[OFF_BM2 + lane];
            #pragma unroll
            for (int d = 0; d < 8; d++) a += S.M1s[t][d] * S.warr[OFF_WM2 + d * 16 + lane];
            S.s_in[t][lane] = leaky_(a);
        } else {
            int j = lane - 16;
            float a = S.warr[OFF_BT2 + j];
            #pragma unroll
            for (int d = 0; d < 8; d++) a += S.T1s[t][d] * S.warr[OFF_WT2 + d * 16 + j];
            float v = fabsf(leaky_(a));
            S.s_in[t][16 + j] = v;
            S.s_in[t][32 + j] = log1pf(v);
        }
        __syncwarp();
        {   // S1 58->32, fully unrolled, 2 accumulators
            float a0 = S.warr[OFF_BS1 + lane], a1 = 0.f;
            #pragma unroll
            for (int d = 0; d < 58; d += 2) {
                a0 += S.s_in[t][d]     * S.warr[OFF_WS1 + d * 32 + lane];
                a1 += S.s_in[t][d + 1] * S.warr[OFF_WS1 + (d + 1) * 32 + lane];
            }
            S.S1s[t][lane] = leaky_(a0 + a1);
        }
        __syncwarp();
        {   // S2 32->64 + lin[0:49] copy
            float a0 = S.warr[OFF_BS2 + lane], a1 = S.warr[OFF_BS2 + 32 + lane];
            #pragma unroll
            for (int d = 0; d < 32; d++) {
                float s = S.S1s[t][d];
                a0 += s * S.warr[OFF_WS2 + d * 64 + lane];
                a1 += s * S.warr[OFF_WS2 + d * 64 + 32 + lane];
            }
            S.lin[t][49 + lane] = leaky_(a0);
            S.lin[t][81 + lane] = leaky_(a1);
            S.lin[t][lane] = S.s_in[t][lane];
            if (lane < 17) S.lin[t][32 + lane] = S.s_in[t][32 + lane];
        }
    }
    CP_WAIT(1);          // Wk slice landed
    __syncthreads();

    // ---- zx = lin @ Wk[:,slice] + b_l : staged smem, transposed map + lin float4 ----
    // dcz = row-block group (8), jqz = col within warp (4). Per thread: 12 LDS.128
    // on lin + 16 LDS.128 on WkS4 (bank-clean: dcz step = 16 banks, jqz step = 4).
    {
        const int dcz = lane >> 2, jqz = lane & 3;
        const int c4z = w * 4 + jqz;                // slice float4-col 0..31
        const float4* lin40 = (const float4*)S.lin[0];
        const float4* lin41 = (const float4*)S.lin[1];
        const float4* lin42 = (const float4*)S.lin[2];
        float4 a0 = {0,0,0,0}, a1 = {0,0,0,0}, a2 = {0,0,0,0};
        #pragma unroll
        for (int j = 0; j < 4; j++) {
            const int r = dcz + 8 * j;              // 4-row block: rows 4r..4r+3
            float l0[4], l1[4], l2[4];
            *(float4*)l0 = lin40[r];                // lin pad cols zeroed
            *(float4*)l1 = lin41[r];
            *(float4*)l2 = lin42[r];
            #pragma unroll
            for (int i = 0; i < 4; i++) {
                const int d = 4 * r + i;            // Wk pad rows 124..127 zeroed
                float4 wv = S.WkS4[d * WSTRIDE + c4z];
                a0.x += l0[i] * wv.x; a0.y += l0[i] * wv.y; a0.z += l0[i] * wv.z; a0.w += l0[i] * wv.w;
                a1.x += l1[i] * wv.x; a1.y += l1[i] * wv.y; a1.z += l1[i] * wv.z; a1.w += l1[i] * wv.w;
                a2.x += l2[i] * wv.x; a2.y += l2[i] * wv.y; a2.z += l2[i] * wv.z; a2.w += l2[i] * wv.w;
            }
        }
        #pragma unroll
        for (int off = 16; off >= 4; off >>= 1) {
            a0.x += __shfl_down_sync(0xffffffffu, a0.x, off);
            a0.y += __shfl_down_sync(0xffffffffu, a0.y, off);
            a0.z += __shfl_down_sync(0xffffffffu, a0.z, off);
            a0.w += __shfl_down_sync(0xffffffffu, a0.w, off);
            a1.x += __shfl_down_sync(0xffffffffu, a1.x, off);
            a1.y += __shfl_down_sync(0xffffffffu, a1.y, off);
            a1.z += __shfl_down_sync(0xffffffffu, a1.z, off);
            a1.w += __shfl_down_sync(0xffffffffu, a1.w, off);
            a2.x += __shfl_down_sync(0xffffffffu, a2.x, off);
            a2.y += __shfl_down_sync(0xffffffffu, a2.y, off);
            a2.z += __shfl_down_sync(0xffffffffu, a2.z, off);
            a2.w += __shfl_down_sync(0xffffffffu, a2.w, off);
        }
        if (lane < 4) {                             // lanes 0..3 hold cols w*4+lane
            const int cc = w * 4 + lane;
            const int gg = ((cc >> 3) * 32) + rank * 8 + (cc & 7);
            float4 blv = ((const float4*)(S.warr + OFF_BL))[gg];
            float4 r0 = {a0.x + blv.x, a0.y + blv.y, a0.z + blv.z, a0.w + blv.w};
            float4 r1 = {a1.x + blv.x, a1.y + blv.y, a1.z + blv.z, a1.w + blv.w};
            float4 r2 = {a2.x + blv.x, a2.y + blv.y, a2.z + blv.z, a2.w + blv.w};
            S.zxs4[0][cc] = r0; S.zxs4[1][cc] = r1; S.zxs4[2][cc] = r2;
        }
    }
    __syncthreads();
    asm volatile("barrier.cluster.wait.aligned;" ::: "memory");    // peers' mbar inited

    const float* zxs0 = (const float*)S.zxs4[0];
    const float* zxs1 = (const float*)S.zxs4[1];
    const float* zxs2 = (const float*)S.zxs4[2];
    float* zbuf = (float*)S.zbuf4;

    // ---- t = 0: gates from zx only; exchange -> hb[0]; phase 0 ----
    float creg = 0.f;
    if (tid < 32) {
        float zi = zxs0[tid];
        float zg = zxs0[64 + tid], zo = zxs0[96 + tid];
        creg = sigm_(zi) * leaky_(zg);
        float hv = sigm_(zo) * leaky_(creg);
        unsigned laddr = smem_u32_(&S.hb[0][rank * 32 + lane]);
        #pragma unroll
        for (unsigned p = 0; p < 4; p++) st_cluster_f32_(laddr, p, hv);
        __syncwarp();
        if (lane < 4) mbar_arrive_rel_(mb, (unsigned)lane);
    }
    CP_WAIT(0);          // Wr slice (+W_P1) landed
    mbar_wait_parity_(mb, 0u);

    // ---- t = 1, 2 ----
    #pragma unroll
    for (int t = 1; t <= 2; t++) {
        const int bufR = (t - 1) & 1, bufW = t & 1;
        {
            float4 acc = {0,0,0,0};
            #pragma unroll
            for (int k = 0; k < 16; k++) {
                int d = dc + 8 * k;
                float4 wv = S.WrS4[d * WSTRIDE + c4];
                float hv = S.hb[bufR][d];
                acc.x += hv * wv.x; acc.y += hv * wv.y;
                acc.z += hv * wv.z; acc.w += hv * wv.w;
            }
            #pragma unroll
            for (int off = 4; off >= 1; off >>= 1) {
                acc.x += __shfl_down_sync(0xffffffffu, acc.x, off);
                acc.y += __shfl_down_sync(0xffffffffu, acc.y, off);
                acc.z += __shfl_down_sync(0xffffffffu, acc.z, off);
                acc.w += __shfl_down_sync(0xffffffffu, acc.w, off);
            }
            if (dc == 0) S.zbuf4[c4] = acc;
        }
        __syncthreads();   // all local reads of hb[bufR] done before arrive below
        if (tid < 32) {
            const float* zxt = (t == 1) ? zxs1 : zxs2;
            float zi = zxt[tid]      + zbuf[tid];
            float zf = zxt[32 + tid] + zbuf[32 + tid];
            float zg = zxt[64 + tid] + zbuf[64 + tid];
            float zo = zxt[96 + tid] + zbuf[96 + tid];
            creg = sigm_(zf) * creg + sigm_(zi) * leaky_(zg);
            float hv = sigm_(zo) * leaky_(creg);
            unsigned laddr = smem_u32_(&S.hb[bufW][rank * 32 + lane]);
            if (t == 1) {
                #pragma unroll
                for (unsigned p = 0; p < 4; p++) st_cluster_f32_(laddr, p, hv);
                __syncwarp();
                if (lane < 4) mbar_arrive_rel_(mb, (unsigned)lane);
            } else {
                // t=2: only rank 0 consumes h (head MLP) — store/arrive at rank 0 only.
                st_cluster_f32_(laddr, 0u, hv);
                __syncwarp();
                if (lane == 0) mbar_arrive_rel_(mb, 0u);
            }
        }
        if (t == 1) mbar_wait_parity_(mb, 1u);
    }

    // ---- Head MLP + softmax + outputs: rank 0 only; final h in hb[0] ----
    // Ranks 1..3 exit now (their mbars never flip phase 2).
    if (rank == 0) {
        mbar_wait_parity_(mb, 0u);   // 4 arrives of phase 2 (acquire covers h stores)
        if (tid < 128) {   // P1: 128->64, warp-split from padded smem
            const int w4 = tid >> 5, l = tid & 31;
            const int pjq = l & 3, pdc = l >> 2;
            const int j4 = w4 * 4 + pjq;
            const float4* Wp1s = (const float4*)(S.warr + OFF_WP1);  // row stride 17 f4
            float4 acc = {0,0,0,0};
            #pragma unroll
            for (int dd = 0; dd < 16; dd++) {
                int d = pdc * 16 + ((dd + pdc) & 15);
                float4 wv = Wp1s[d * 17 + j4];
                float hv = S.hb[0][d];
                acc.x += hv * wv.x; acc.y += hv * wv.y;
                acc.z += hv * wv.z; acc.w += hv * wv.w;
            }
            #pragma unroll
            for (int off = 16; off >= 4; off >>= 1) {
                acc.x += __shfl_down_sync(0xffffffffu, acc.x, off);
                acc.y += __shfl_down_sync(0xffffffffu, acc.y, off);
                acc.z += __shfl_down_sync(0xffffffffu, acc.z, off);
                acc.w += __shfl_down_sync(0xffffffffu, acc.w, off);
            }
            if (l < 4) {
                int jb = (w4 * 4 + l) * 4;
                const float4 bp = ((const float4*)(S.warr + OFF_BP1))[w4 * 4 + l];
                S.d1[jb + 0] = leaky_(acc.x + bp.x);
                S.d1[jb + 1] = leaky_(acc.y + bp.y);
                S.d1[jb + 2] = leaky_(acc.z + bp.z);
                S.d1[jb + 3] = leaky_(acc.w + bp.w);
            }
        }
        __syncthreads();
        if (w == 0) {
            {   // P2: 64->32, fully unrolled, 2 accumulators
                float a0 = S.warr[OFF_BP2 + lane], a1 = 0.f;
                #pragma unroll
                for (int d = 0; d < 64; d += 2) {
                    a0 += S.d1[d]     * S.warr[OFF_WP2 + d * 32 + lane];
                    a1 += S.d1[d + 1] * S.warr[OFF_WP2 + (d + 1) * 32 + lane];
                }
                S.d2[lane] = leaky_(a0 + a1);
            }
            __syncwarp();
            if (lane < 16) {   // P3: 32->16, fully unrolled, 2 accumulators
                float a0 = S.warr[OFF_BP3 + lane], a1 = 0.f;
                #pragma unroll
                for (int d = 0; d < 32; d += 2) {
                    a0 += S.d2[d]     * S.warr[OFF_WP3 + d * 16 + lane];
                    a1 += S.d2[d + 1] * S.warr[OFF_WP3 + (d + 1) * 16 + lane];
                }
                S.d3[lane] = leaky_(a0 + a1);
            }
            __syncwarp();
            if (lane < 8) {
                float a = S.warr[OFF_BP4 + lane];
                #pragma unroll
                for (int d = 0; d < 16; d++) a += S.d3[d] * S.warr[OFF_WP4 + d * 8 + lane];
                S.d4[lane] = leaky_(a);
            }
            __syncwarp();
            if (lane < 3) {
                float a = S.warr[OFF_BP5 + lane];
                #pragma unroll
                for (int d = 0; d < 8; d++) a += S.d4[d] * S.warr[OFF_WP5 + d * 3 + lane];
                S.d5[lane] = leaky_(a);
            }
            __syncwarp();
            if (lane == 0) {
                float m = fmaxf(S.d5[0], fmaxf(S.d5[1], S.d5[2]));
                float e0 = __expf(S.d5[0] - m), e1 = __expf(S.d5[1] - m), e2 = __expf(S.d5[2] - m);
                float s = e0 + e1 + e2;
                float inv = __fdividef(1.f, s);
                S.probs[0] = e0 * inv; S.probs[1] = e1 * inv; S.probs[2] = e2 * inv;
            }
            __syncwarp();
            if (lane < 3) out[b * 3 + lane] = S.probs[lane];
            if (lane >= 4 && lane < 17) {
                int k = lane - 4;
                out[96 + b * 13 + k] = (k < 10) ? S.xs[2][1 + k] : S.probs[k - 10];
            }
        }
    }
}

extern "C" void kernel_launch(void* const* d_in, const int* in_sizes, int n_in,
                              void* d_out, int out_size) {
    const float* data = (const float*)d_in[0];
    const float* W_M1 = (const float*)d_in[1];  const float* b_M1 = (const float*)d_in[2];
    const float* W_M2 = (const float*)d_in[3];  const float* b_M2 = (const float*)d_in[4];
    const float* W_T1 = (const float*)d_in[5];  const float* b_T1 = (const float*)d_in[6];
    const float* W_T2 = (const float*)d_in[7];  const float* b_T2 = (const float*)d_in[8];
    const float* W_S1 = (const float*)d_in[9];  const float* b_S1 = (const float*)d_in[10];
    const float* W_S2 = (const float*)d_in[11]; const float* b_S2 = (const float*)d_in[12];
    const float* Wk   = (const float*)d_in[13];
    const float* Wr   = (const float*)d_in[14];
    const float* b_l  = (const float*)d_in[15];
    const float* W_P1 = (const float*)d_in[16]; const float* b_P1 = (const float*)d_in[17];
    const float* W_P2 = (const float*)d_in[18]; const float* b_P2 = (const float*)d_in[19];
    const float* W_P3 = (const float*)d_in[20]; const float* b_P3 = (const float*)d_in[21];
    const float* W_P4 = (const float*)d_in[22]; const float* b_P4 = (const float*)d_in[23];
    const float* W_P5 = (const float*)d_in[24]; const float* b_P5 = (const float*)d_in[25];
    float* out = (float*)d_out;

    cudaFuncSetAttribute(lstm_t2_kernel,
                         cudaFuncAttributeMaxDynamicSharedMemorySize,
                         (int)sizeof(SmemT));

    lstm_t2_kernel<<<128, 256, sizeof(SmemT)>>>(data,
        W_M1, b_M1, W_M2, b_M2, W_T1, b_T1, W_T2, b_T2,
        W_S1, b_S1, W_S2, b_S2, Wk, Wr, b_l,
        W_P1, b_P1, W_P2, b_P2, W_P3, b_P3, W_P4, b_P4, W_P5, b_P5,
        out);
}

// round 16
// speedup vs baseline: 1.0201x; 1.0201x over previous
#include <cuda_runtime.h>
#include <math.h>

#define LEAK 0.2f

__device__ __forceinline__ float leaky_(float x) { return x >= 0.f ? x : LEAK * x; }
__device__ __forceinline__ float sigm_(float x) {
    float e = __expf(-x);
    return __fdividef(1.f, 1.f + e);
}

// Shared weight-arena offsets (floats)
#define OFF_WM1 0
#define OFF_BM1 48
#define OFF_WM2 56
#define OFF_BM2 184
#define OFF_WT1 200
#define OFF_BT1 288
#define OFF_WT2 296
#define OFF_BT2 424
#define OFF_WS1 440
#define OFF_BS1 2296
#define OFF_WS2 2328
#define OFF_BS2 4376
#define OFF_WP2 4440
#define OFF_BP2 6488
#define OFF_WP3 6520
#define OFF_BP3 7032
#define OFF_WP4 7048
#define OFF_BP4 7176
#define OFF_WP5 7184
#define OFF_BP5 7208
#define OFF_BL  7212              /* 512 floats */
#define OFF_BP1 7724              /* 64 floats */
#define OFF_WP1 7788              /* 128 rows x 68 floats (stride-17 float4, padded) */
#define ARENA_SZ (7788 + 128 * 68)

#define WSTRIDE 33   // float4 row stride for Wk/Wr slices (pad kills bank conflicts)

struct SmemT {
    float4 WkS4[128 * WSTRIDE];     // Wk column slice (rows 124..127 zeroed)
    float4 WrS4[128 * WSTRIDE];     // Wr column slice
    float4 zxs4[3][32];             // zx slice per t (includes b_l)
    float4 zbuf4[32];               // recurrence matvec partial
    float  hb[2][128];              // double-buffered full h
    float  warr[ARENA_SZ];          // small weights + b_l + b_P1 + padded W_P1
    unsigned long long mbar;
    float  xs[3][11];
    float  M1s[3][8], T1s[3][8];
    float  s_in[3][58];
    float  S1s[3][32];
    float  lin[3][128];             // cols 124..127 zeroed
    float  d1[64], d2[32], d3[16], d4[8], d5[3], probs[3];
};

__device__ __forceinline__ unsigned smem_u32_(const void* p) {
    unsigned a;
    asm("{ .reg .u64 t; cvta.to.shared.u64 t, %1; cvt.u32.u64 %0, t; }" : "=r"(a) : "l"(p));
    return a;
}
__device__ __forceinline__ void cpa16_(unsigned dst, const void* src) {
    asm volatile("cp.async.cg.shared.global [%0], [%1], 16;" :: "r"(dst), "l"(src) : "memory");
}
#define CP_COMMIT() asm volatile("cp.async.commit_group;" ::: "memory")
#define CP_WAIT(n)  asm volatile("cp.async.wait_group %0;" :: "n"(n) : "memory")

__device__ __forceinline__ void st_cluster_f32_(unsigned laddr, unsigned rank, float v) {
    asm volatile("{ .reg .b32 r; mapa.shared::cluster.u32 r, %0, %1; st.shared::cluster.f32 [r], %2; }"
                 :: "r"(laddr), "r"(rank), "f"(v) : "memory");
}
__device__ __forceinline__ void mbar_arrive_rel_(unsigned mb_local, unsigned rank) {
    asm volatile("{ .reg .b32 r; mapa.shared::cluster.u32 r, %0, %1;\n\t"
                 "mbarrier.arrive.release.cluster.shared::cluster.b64 _, [r]; }"
                 :: "r"(mb_local), "r"(rank) : "memory");
}
__device__ __forceinline__ void mbar_wait_parity_(unsigned mb, unsigned parity) {
    asm volatile(
        "{\n\t.reg .pred P;\n"
        "WL_%=:\n\t"
        "mbarrier.try_wait.parity.acquire.cluster.shared::cta.b64 P, [%0], %1, 0x989680;\n\t"
        "@P bra.uni WD_%=;\n\t"
        "bra.uni WL_%=;\n"
        "WD_%=:\n\t}"
        :: "r"(mb), "r"(parity) : "memory");
}

// 4 CTAs per batch (cluster). Rank r owns h[32r..32r+32) and the matching
// z-columns of each i/f/g/o strip. Only timesteps 0..2 matter (out = out[:,2:3,:]).
__global__ __launch_bounds__(256, 1) __cluster_dims__(4, 1, 1)
void lstm_t2_kernel(
    const float* __restrict__ data,
    const float* __restrict__ W_M1, const float* __restrict__ b_M1,
    const float* __restrict__ W_M2, const float* __restrict__ b_M2,
    const float* __restrict__ W_T1, const float* __restrict__ b_T1,
    const float* __restrict__ W_T2, const float* __restrict__ b_T2,
    const float* __restrict__ W_S1, const float* __restrict__ b_S1,
    const float* __restrict__ W_S2, const float* __restrict__ b_S2,
    const float* __restrict__ Wk,   // (124,512)
    const float* __restrict__ Wr,   // (128,512)
    const float* __restrict__ b_l,  // (512)
    const float* __restrict__ W_P1, const float* __restrict__ b_P1,
    const float* __restrict__ W_P2, const float* __restrict__ b_P2,
    const float* __restrict__ W_P3, const float* __restrict__ b_P3,
    const float* __restrict__ W_P4, const float* __restrict__ b_P4,
    const float* __restrict__ W_P5, const float* __restrict__ b_P5,
    float* __restrict__ out)
{
    extern __shared__ char smraw[];
    SmemT& S = *reinterpret_cast<SmemT*>(smraw);

    const int tid  = threadIdx.x;
    const int w    = tid >> 5, lane = tid & 31;
    const int b    = blockIdx.x >> 2;
    const int rank = blockIdx.x & 3;
    const int T = 4096, F = 11;

    // matvec lane map: dc = row-chunk (8 lanes), jq = float4-col within warp (4 cols)
    const int dc = lane & 7, jq = lane >> 3;
    const int c4  = w * 4 + jq;                                 // slice float4-col 0..31
    const int gc4 = ((c4 >> 3) * 32) + rank * 8 + (c4 & 7);     // global float4-col
    // staging map: this thread stages slice col `lane` <-> global col gmap (coalesced in 8-lane groups)
    const int gmap = ((lane >> 3) * 32) + rank * 8 + (lane & 7);

    const unsigned warr_b = smem_u32_(S.warr);
    const unsigned wk_b   = smem_u32_(S.WkS4);
    const unsigned wr_b   = smem_u32_(S.WrS4);
    const unsigned mb     = smem_u32_(&S.mbar);

    if (tid == 0)
        asm volatile("mbarrier.init.shared.b64 [%0], %1;" :: "r"(mb), "r"(4u) : "memory");

    // ---- Group 1: arena (+ b_l, b_P1) ----
#define ACPY(off, src, nfl) { const float4* s4_ = (const float4*)(src); \
    for (int i = tid; i < (nfl) / 4; i += 256) cpa16_(warr_b + ((off) + i * 4) * 4, s4_ + i); }
    ACPY(OFF_WM1, W_M1, 48)   ACPY(OFF_BM1, b_M1, 8)
    ACPY(OFF_WM2, W_M2, 128)  ACPY(OFF_BM2, b_M2, 16)
    ACPY(OFF_WT1, W_T1, 88)   ACPY(OFF_BT1, b_T1, 8)
    ACPY(OFF_WT2, W_T2, 128)  ACPY(OFF_BT2, b_T2, 16)
    ACPY(OFF_WS1, W_S1, 1856) ACPY(OFF_BS1, b_S1, 32)
    ACPY(OFF_WS2, W_S2, 2048) ACPY(OFF_BS2, b_S2, 64)
    ACPY(OFF_BL,  b_l,  512)
    if (rank == 0) {
        ACPY(OFF_WP2, W_P2, 2048) ACPY(OFF_BP2, b_P2, 32)
        ACPY(OFF_WP3, W_P3, 512)  ACPY(OFF_BP3, b_P3, 16)
        ACPY(OFF_WP4, W_P4, 128)  ACPY(OFF_BP4, b_P4, 8)
        ACPY(OFF_WP5, W_P5, 24)   ACPY(OFF_BP1, b_P1, 64)
    }
#undef ACPY
    CP_COMMIT();

    // ---- Group 2: Wk slice ----
    {
        const float4* Wk4 = (const float4*)Wk;   // row stride 128 float4
        #pragma unroll
        for (int k = 0; k < 16; k++) {
            int d = w + 8 * k;
            if (d < 124) cpa16_(wk_b + (d * WSTRIDE + lane) * 16, Wk4 + (size_t)d * 128 + gmap);
        }
    }
    CP_COMMIT();

    // ---- Group 3: Wr slice + padded W_P1 ----
    {
        const float4* Wr4 = (const float4*)Wr;
        #pragma unroll
        for (int k = 0; k < 16; k++) {
            int d = w + 8 * k;
            cpa16_(wr_b + (d * WSTRIDE + lane) * 16, Wr4 + (size_t)d * 128 + gmap);
        }
        if (rank == 0) {
            const float4* Wp14 = (const float4*)W_P1;  // row stride 16 float4
            for (int i = tid; i < 2048; i += 256) {    // 128 rows x 16 chunks
                int row = i >> 4, c = i & 15;
                cpa16_(warr_b + (OFF_WP1 + row * 68 + c * 4) * 4, Wp14 + row * 16 + c);
            }
        }
    }
    CP_COMMIT();

    // zero Wk pad rows, lin pad cols, inputs, b_P5 (all overlapped with cp.async)
    if (tid < 132) {
        float4 z = {0.f, 0.f, 0.f, 0.f};
        S.WkS4[(124 + tid / 33) * WSTRIDE + tid % 33] = z;
    } else if (tid >= 160 && tid < 172) {
        int i = tid - 160;
        S.lin[i >> 2][124 + (i & 3)] = 0.f;
    } else if (tid >= 192 && tid < 195) {
        S.warr[OFF_BP5 + tid - 192] = b_P5[tid - 192];
    }
    if (tid < 33) {
        int t = tid / 11, k = tid % 11;
        S.xs[t][k] = data[((size_t)b * T + t) * F + k];
    }

    CP_WAIT(2);          // arena landed
    __syncthreads();
    asm volatile("barrier.cluster.arrive.aligned;" ::: "memory");  // publish mbar init

    // ---- Prologue: warp t (t<3) runs the whole per-timestep chain, warp-local ----
    if (w < 3) {
        const int t = w;
        // stage 1: M1 | T1 | raw copies (xs already in smem)
        if (lane < 8) {
            float a = S.warr[OFF_BM1 + lane];
            #pragma unroll
            for (int d = 0; d < 6; d++) a += S.xs[t][4 + d] * S.warr[OFF_WM1 + d * 8 + lane];
            S.M1s[t][lane] = leaky_(a);
        } else if (lane < 16) {
            int j = lane - 8;
            float a = S.warr[OFF_BT1 + j];
            #pragma unroll
            for (int d = 0; d < 11; d++) a += S.xs[t][d] * S.warr[OFF_WT1 + d * 8 + j];
            S.T1s[t][j] = fabsf(leaky_(a));
        } else if (lane < 27) {
            int k = lane - 16;
            S.lin[t][113 + k] = S.xs[t][k];                 // raw x tail of lstm_in
            if (k < 6) S.s_in[t][52 + k] = S.xs[t][4 + k];  // body
        } else if (lane == 27) {
            S.s_in[t][48] = log1pf(S.xs[t][1]);             // Pa
        } else if (lane < 31) {
            int k = lane - 28;
            S.s_in[t][49 + k] = S.xs[t][1 + k];             // env
        }
        __syncwarp();
        // stage 2: M2 -> s_in[0:16] | T2 -> s_in[16:32] + Psk -> s_in[32:48]
        if (lane < 16) {
            float a = S.warr[OFF_BM2 + lane];
            #pragma unroll
            for (int d = 0; d < 8; d++) a += S.M1s[t][d] * S.warr[OFF_WM2 + d * 16 + lane];
            S.s_in[t][lane] = leaky_(a);
        } else {
            int j = lane - 16;
            float a = S.warr[OFF_BT2 + j];
            #pragma unroll
            for (int d = 0; d < 8; d++) a += S.T1s[t][d] * S.warr[OFF_WT2 + d * 16 + j];
            float v = fabsf(leaky_(a));
            S.s_in[t][16 + j] = v;
            S.s_in[t][32 + j] = log1pf(v);
        }
        __syncwarp();
        // stage 3: S1 58->32, fully unrolled, 2 accumulators
        {
            float a0 = S.warr[OFF_BS1 + lane], a1 = 0.f;
            #pragma unroll
            for (int d = 0; d < 58; d += 2) {
                a0 += S.s_in[t][d]     * S.warr[OFF_WS1 + d * 32 + lane];
                a1 += S.s_in[t][d + 1] * S.warr[OFF_WS1 + (d + 1) * 32 + lane];
            }
            S.S1s[t][lane] = leaky_(a0 + a1);
        }
        __syncwarp();
        // stage 4: S2 32->64 (two outputs per lane) + lin[0:49] copy
        {
            float a0 = S.warr[OFF_BS2 + lane], a1 = S.warr[OFF_BS2 + 32 + lane];
            #pragma unroll
            for (int d = 0; d < 32; d++) {
                float s = S.S1s[t][d];
                a0 += s * S.warr[OFF_WS2 + d * 64 + lane];
                a1 += s * S.warr[OFF_WS2 + d * 64 + 32 + lane];
            }
            S.lin[t][49 + lane] = leaky_(a0);
            S.lin[t][81 + lane] = leaky_(a1);
            S.lin[t][lane] = S.s_in[t][lane];
            if (lane < 17) S.lin[t][32 + lane] = S.s_in[t][32 + lane];
        }
    }
    CP_WAIT(1);          // Wk slice landed
    __syncthreads();

    // ---- zx = lin @ Wk[:,slice] + b_l : branchless smem matvec, shfl-reduced ----
    {
        float4 a0 = {0,0,0,0}, a1 = {0,0,0,0}, a2 = {0,0,0,0};
        #pragma unroll
        for (int k = 0; k < 16; k++) {
            int d = dc + 8 * k;
            float4 wv = S.WkS4[d * WSTRIDE + c4];
            float l0 = S.lin[0][d], l1 = S.lin[1][d], l2 = S.lin[2][d];
            a0.x += l0 * wv.x; a0.y += l0 * wv.y; a0.z += l0 * wv.z; a0.w += l0 * wv.w;
            a1.x += l1 * wv.x; a1.y += l1 * wv.y; a1.z += l1 * wv.z; a1.w += l1 * wv.w;
            a2.x += l2 * wv.x; a2.y += l2 * wv.y; a2.z += l2 * wv.z; a2.w += l2 * wv.w;
        }
        #pragma unroll
        for (int off = 4; off >= 1; off >>= 1) {
            a0.x += __shfl_down_sync(0xffffffffu, a0.x, off);
            a0.y += __shfl_down_sync(0xffffffffu, a0.y, off);
            a0.z += __shfl_down_sync(0xffffffffu, a0.z, off);
            a0.w += __shfl_down_sync(0xffffffffu, a0.w, off);
            a1.x += __shfl_down_sync(0xffffffffu, a1.x, off);
            a1.y += __shfl_down_sync(0xffffffffu, a1.y, off);
            a1.z += __shfl_down_sync(0xffffffffu, a1.z, off);
            a1.w += __shfl_down_sync(0xffffffffu, a1.w, off);
            a2.x += __shfl_down_sync(0xffffffffu, a2.x, off);
            a2.y += __shfl_down_sync(0xffffffffu, a2.y, off);
            a2.z += __shfl_down_sync(0xffffffffu, a2.z, off);
            a2.w += __shfl_down_sync(0xffffffffu, a2.w, off);
        }
        if (dc == 0) {
            float4 blv = ((const float4*)(S.warr + OFF_BL))[gc4];
            float4 r0 = {a0.x + blv.x, a0.y + blv.y, a0.z + blv.z, a0.w + blv.w};
            float4 r1 = {a1.x + blv.x, a1.y + blv.y, a1.z + blv.z, a1.w + blv.w};
            float4 r2 = {a2.x + blv.x, a2.y + blv.y, a2.z + blv.z, a2.w + blv.w};
            S.zxs4[0][c4] = r0; S.zxs4[1][c4] = r1; S.zxs4[2][c4] = r2;
        }
    }
    __syncthreads();
    asm volatile("barrier.cluster.wait.aligned;" ::: "memory");    // peers' mbar inited

    const float* zxs0 = (const float*)S.zxs4[0];
    const float* zxs1 = (const float*)S.zxs4[1];
    const float* zxs2 = (const float*)S.zxs4[2];
    float* zbuf = (float*)S.zbuf4;

    // ---- t = 0: gates from zx only; exchange -> hb[0]; phase 0 ----
    float creg = 0.f;
    if (tid < 32) {
        float zi = zxs0[tid];
        float zg = zxs0[64 + tid], zo = zxs0[96 + tid];
        creg = sigm_(zi) * leaky_(zg);
        float hv = sigm_(zo) * leaky_(creg);
        unsigned laddr = smem_u32_(&S.hb[0][rank * 32 + lane]);
        #pragma unroll
        for (unsigned p = 0; p < 4; p++) st_cluster_f32_(laddr, p, hv);
        __syncwarp();
        if (lane < 4) mbar_arrive_rel_(mb, (unsigned)lane);
    }
    CP_WAIT(0);          // Wr slice (+W_P1) landed
    mbar_wait_parity_(mb, 0u);

    // ---- t = 1, 2 ----
    #pragma unroll
    for (int t = 1; t <= 2; t++) {
        const int bufR = (t - 1) & 1, bufW = t & 1;
        {
            float4 acc = {0,0,0,0};
            #pragma unroll
            for (int k = 0; k < 16; k++) {
                int d = dc + 8 * k;
                float4 wv = S.WrS4[d * WSTRIDE + c4];
                float hv = S.hb[bufR][d];
                acc.x += hv * wv.x; acc.y += hv * wv.y;
                acc.z += hv * wv.z; acc.w += hv * wv.w;
            }
            #pragma unroll
            for (int off = 4; off >= 1; off >>= 1) {
                acc.x += __shfl_down_sync(0xffffffffu, acc.x, off);
                acc.y += __shfl_down_sync(0xffffffffu, acc.y, off);
                acc.z += __shfl_down_sync(0xffffffffu, acc.z, off);
                acc.w += __shfl_down_sync(0xffffffffu, acc.w, off);
            }
            if (dc == 0) S.zbuf4[c4] = acc;
        }
        __syncthreads();   // all local reads of hb[bufR] done before arrive below
        if (tid < 32) {
            const float* zxt = (t == 1) ? zxs1 : zxs2;
            float zi = zxt[tid]      + zbuf[tid];
            float zf = zxt[32 + tid] + zbuf[32 + tid];
            float zg = zxt[64 + tid] + zbuf[64 + tid];
            float zo = zxt[96 + tid] + zbuf[96 + tid];
            creg = sigm_(zf) * creg + sigm_(zi) * leaky_(zg);
            float hv = sigm_(zo) * leaky_(creg);
            unsigned laddr = smem_u32_(&S.hb[bufW][rank * 32 + lane]);
            if (t == 1) {
                #pragma unroll
                for (unsigned p = 0; p < 4; p++) st_cluster_f32_(laddr, p, hv);
                __syncwarp();
                if (lane < 4) mbar_arrive_rel_(mb, (unsigned)lane);
            } else {
                // t=2: only rank 0 consumes h (head MLP) — store/arrive at rank 0 only.
                st_cluster_f32_(laddr, 0u, hv);
                __syncwarp();
                if (lane == 0) mbar_arrive_rel_(mb, 0u);
            }
        }
        if (t == 1) mbar_wait_parity_(mb, 1u);
    }

    // ---- Head MLP + softmax + outputs: rank 0 only; final h in hb[0] ----
    // Ranks 1..3 exit now (their mbars never flip phase 2).
    if (rank == 0) {
        mbar_wait_parity_(mb, 0u);   // 4 arrives of phase 2 (acquire covers h stores)
        if (tid < 128) {   // P1: 128->64, warp-split from padded smem
            const int w4 = tid >> 5, l = tid & 31;
            const int pjq = l & 3, pdc = l >> 2;
            const int j4 = w4 * 4 + pjq;
            const float4* Wp1s = (const float4*)(S.warr + OFF_WP1);  // row stride 17 f4
            float4 acc = {0,0,0,0};
            #pragma unroll
            for (int dd = 0; dd < 16; dd++) {
                int d = pdc * 16 + ((dd + pdc) & 15);
                float4 wv = Wp1s[d * 17 + j4];
                float hv = S.hb[0][d];
                acc.x += hv * wv.x; acc.y += hv * wv.y;
                acc.z += hv * wv.z; acc.w += hv * wv.w;
            }
            #pragma unroll
            for (int off = 16; off >= 4; off >>= 1) {
                acc.x += __shfl_down_sync(0xffffffffu, acc.x, off);
                acc.y += __shfl_down_sync(0xffffffffu, acc.y, off);
                acc.z += __shfl_down_sync(0xffffffffu, acc.z, off);
                acc.w += __shfl_down_sync(0xffffffffu, acc.w, off);
            }
            if (l < 4) {
                int jb = (w4 * 4 + l) * 4;
                const float4 bp = ((const float4*)(S.warr + OFF_BP1))[w4 * 4 + l];
                S.d1[jb + 0] = leaky_(acc.x + bp.x);
                S.d1[jb + 1] = leaky_(acc.y + bp.y);
                S.d1[jb + 2] = leaky_(acc.z + bp.z);
                S.d1[jb + 3] = leaky_(acc.w + bp.w);
            }
        }
        __syncthreads();
        if (w == 0) {
            {   // P2: 64->32, fully unrolled, 2 accumulators
                float a0 = S.warr[OFF_BP2 + lane], a1 = 0.f;
                #pragma unroll
                for (int d = 0; d < 64; d += 2) {
                    a0 += S.d1[d]     * S.warr[OFF_WP2 + d * 32 + lane];
                    a1 += S.d1[d + 1] * S.warr[OFF_WP2 + (d + 1) * 32 + lane];
                }
                S.d2[lane] = leaky_(a0 + a1);
            }
            __syncwarp();
            if (lane < 16) {   // P3: 32->16, fully unrolled, 2 accumulators
                float a0 = S.warr[OFF_BP3 + lane], a1 = 0.f;
                #pragma unroll
                for (int d = 0; d < 32; d += 2) {
                    a0 += S.d2[d]     * S.warr[OFF_WP3 + d * 16 + lane];
                    a1 += S.d2[d + 1] * S.warr[OFF_WP3 + (d + 1) * 16 + lane];
                }
                S.d3[lane] = leaky_(a0 + a1);
            }
            __syncwarp();
            if (lane < 8) {
                float a = S.warr[OFF_BP4 + lane];
                #pragma unroll
                for (int d = 0; d < 16; d++) a += S.d3[d] * S.warr[OFF_WP4 + d * 8 + lane];
                S.d4[lane] = leaky_(a);
            }
            __syncwarp();
            if (lane < 3) {
                float a = S.warr[OFF_BP5 + lane];
                #pragma unroll
                for (int d = 0; d < 8; d++) a += S.d4[d] * S.warr[OFF_WP5 + d * 3 + lane];
                S.d5[lane] = leaky_(a);
            }
            __syncwarp();
            if (lane == 0) {
                float m = fmaxf(S.d5[0], fmaxf(S.d5[1], S.d5[2]));
                float e0 = __expf(S.d5[0] - m), e1 = __expf(S.d5[1] - m), e2 = __expf(S.d5[2] - m);
                float s = e0 + e1 + e2;
                float inv = __fdividef(1.f, s);
                S.probs[0] = e0 * inv; S.probs[1] = e1 * inv; S.probs[2] = e2 * inv;
            }
            __syncwarp();
            if (lane < 3) out[b * 3 + lane] = S.probs[lane];
            if (lane >= 4 && lane < 17) {
                int k = lane - 4;
                out[96 + b * 13 + k] = (k < 10) ? S.xs[2][1 + k] : S.probs[k - 10];
            }
        }
    }
}

extern "C" void kernel_launch(void* const* d_in, const int* in_sizes, int n_in,
                              void* d_out, int out_size) {
    const float* data = (const float*)d_in[0];
    const float* W_M1 = (const float*)d_in[1];  const float* b_M1 = (const float*)d_in[2];
    const float* W_M2 = (const float*)d_in[3];  const float* b_M2 = (const float*)d_in[4];
    const float* W_T1 = (const float*)d_in[5];  const float* b_T1 = (const float*)d_in[6];
    const float* W_T2 = (const float*)d_in[7];  const float* b_T2 = (const float*)d_in[8];
    const float* W_S1 = (const float*)d_in[9];  const float* b_S1 = (const float*)d_in[10];
    const float* W_S2 = (const float*)d_in[11]; const float* b_S2 = (const float*)d_in[12];
    const float* Wk   = (const float*)d_in[13];
    const float* Wr   = (const float*)d_in[14];
    const float* b_l  = (const float*)d_in[15];
    const float* W_P1 = (const float*)d_in[16]; const float* b_P1 = (const float*)d_in[17];
    const float* W_P2 = (const float*)d_in[18]; const float* b_P2 = (const float*)d_in[19];
    const float* W_P3 = (const float*)d_in[20]; const float* b_P3 = (const float*)d_in[21];
    const float* W_P4 = (const float*)d_in[22]; const float* b_P4 = (const float*)d_in[23];
    const float* W_P5 = (const float*)d_in[24]; const float* b_P5 = (const float*)d_in[25];
    float* out = (float*)d_out;

    cudaFuncSetAttribute(lstm_t2_kernel,
                         cudaFuncAttributeMaxDynamicSharedMemorySize,
                         (int)sizeof(SmemT));

    lstm_t2_kernel<<<128, 256, sizeof(SmemT)>>>(data,
        W_M1, b_M1, W_M2, b_M2, W_T1, b_T1, W_T2, b_T2,
        W_S1, b_S1, W_S2, b_S2, Wk, Wr, b_l,
        W_P1, b_P1, W_P2, b_P2, W_P3, b_P3, W_P4, b_P4, W_P5, b_P5,
        out);
}